// round 2
// baseline (speedup 1.0000x reference)
#include <cuda_runtime.h>
#include <cstdint>

// Problem constants (fixed by the reference)
#define NN 50000      // nodes
#define NE 800000     // edges
#define DI 256        // input / hidden dim
#define DO 128        // output dim

// ---------------- device scratch (static; no runtime alloc) ----------------
__device__ float g_x[NN * DI];       // current node features (ping)
__device__ float g_h[NN * DI];       // post-GEMM features (pong)
__device__ int   g_deg[NN];          // in-degree (edges only)
__device__ float g_dinv[NN];         // rsqrt(deg + 1)
__device__ int   g_rowptr[NN + 1];   // CSR row pointers (by destination)
__device__ int   g_cursor[NN];       // fill cursors
__device__ int   g_col[NE];          // CSR source indices
__device__ float g_norm[NE];         // CSR edge norms dinv[dst]*dinv[src]
__device__ int   g_bsum[64];         // scan block partials

// ---------------- elementwise: x = qe * obj (vectorized) ----------------
__global__ void k_had(const float4* __restrict__ a, const float4* __restrict__ b) {
    int i = blockIdx.x * blockDim.x + threadIdx.x;
    const int n4 = NN * DI / 4;
    if (i < n4) {
        float4 va = a[i], vb = b[i];
        float4 r = make_float4(va.x * vb.x, va.y * vb.y, va.z * vb.z, va.w * vb.w);
        reinterpret_cast<float4*>(g_x)[i] = r;
    }
}

// ---------------- degree / norm prep ----------------
__global__ void k_zero_deg() {
    int i = blockIdx.x * blockDim.x + threadIdx.x;
    if (i < NN) g_deg[i] = 0;
}

__global__ void k_count(const int* __restrict__ ei) {
    int e = blockIdx.x * blockDim.x + threadIdx.x;
    if (e < NE) {
        int r = ei[e];                 // edge_index[0][e] = destination
        atomicAdd(&g_deg[r], 1);
    }
}

__global__ void k_dinv() {
    int i = blockIdx.x * blockDim.x + threadIdx.x;
    if (i < NN) g_dinv[i] = rsqrtf((float)(g_deg[i] + 1));   // +1 self loop
}

// ---------------- exclusive scan of g_deg into g_rowptr ----------------
__global__ __launch_bounds__(1024) void k_scan_block() {
    __shared__ int s[1024];
    int tid = threadIdx.x;
    int i = blockIdx.x * 1024 + tid;
    int v = (i < NN) ? g_deg[i] : 0;
    s[tid] = v;
    __syncthreads();
    #pragma unroll
    for (int off = 1; off < 1024; off <<= 1) {
        int t = (tid >= off) ? s[tid - off] : 0;
        __syncthreads();
        s[tid] += t;
        __syncthreads();
    }
    if (i < NN) g_rowptr[i] = s[tid] - v;       // exclusive within block
    if (tid == 1023) g_bsum[blockIdx.x] = s[1023];
}

__global__ void k_scan_sums(int nblocks) {
    if (blockIdx.x == 0 && threadIdx.x == 0) {
        int acc = 0;
        for (int b = 0; b < nblocks; b++) {
            int v = g_bsum[b];
            g_bsum[b] = acc;
            acc += v;
        }
    }
}

__global__ void k_scan_add() {
    int i = blockIdx.x * blockDim.x + threadIdx.x;
    if (i < NN) {
        int v = g_rowptr[i] + g_bsum[i >> 10];
        g_rowptr[i] = v;
        g_cursor[i] = v;
        if (i == 0) g_rowptr[NN] = NE;
    }
}

// ---------------- CSR fill (col + edge norm) ----------------
__global__ void k_fill(const int* __restrict__ ei) {
    int e = blockIdx.x * blockDim.x + threadIdx.x;
    if (e < NE) {
        int r = ei[e];         // destination
        int c = ei[NE + e];    // source
        int pos = atomicAdd(&g_cursor[r], 1);
        g_col[pos]  = c;
        g_norm[pos] = g_dinv[r] * g_dinv[c];
    }
}

// ---------------- SGEMM: g_h[M,Nn] = g_x[M,K] @ W[K,Nn] ----------------
__global__ __launch_bounds__(256) void k_sgemm(const float* __restrict__ B,
                                               int M, int K, int Nn) {
    constexpr int BM = 128, BN = 128, BK = 16, TM = 8, TN = 8;
    __shared__ float As[BK][BM];
    __shared__ float Bs[BK][BN];

    const float* A = g_x;
    float* C = g_h;

    const int tid = threadIdx.x;
    const int bx = blockIdx.x, by = blockIdx.y;
    const int trow = tid / (BN / TN);   // 0..15
    const int tcol = tid % (BN / TN);   // 0..15

    float acc[TM][TN];
    #pragma unroll
    for (int i = 0; i < TM; i++)
        #pragma unroll
        for (int j = 0; j < TN; j++) acc[i][j] = 0.f;

    const int aRow = tid / (BK / 4);        // 0..63
    const int aCol = (tid % (BK / 4)) * 4;  // 0,4,8,12
    const int bRow = tid / (BN / 4);        // 0..7
    const int bCol = (tid % (BN / 4)) * 4;  // 0..124

    const int rowBase = by * BM;

    for (int k0 = 0; k0 < K; k0 += BK) {
        #pragma unroll
        for (int r = 0; r < BM; r += 64) {
            int gr = rowBase + aRow + r;
            float4 v = (gr < M)
                ? *reinterpret_cast<const float4*>(&A[(size_t)gr * K + k0 + aCol])
                : make_float4(0.f, 0.f, 0.f, 0.f);
            As[aCol + 0][aRow + r] = v.x;
            As[aCol + 1][aRow + r] = v.y;
            As[aCol + 2][aRow + r] = v.z;
            As[aCol + 3][aRow + r] = v.w;
        }
        #pragma unroll
        for (int r = 0; r < BK; r += 8) {
            int gr = k0 + bRow + r;
            *reinterpret_cast<float4*>(&Bs[bRow + r][bCol]) =
                *reinterpret_cast<const float4*>(&B[(size_t)gr * Nn + bx * BN + bCol]);
        }
        __syncthreads();

        #pragma unroll
        for (int kk = 0; kk < BK; kk++) {
            float ar[TM], br[TN];
            #pragma unroll
            for (int i = 0; i < TM; i++) ar[i] = As[kk][trow * TM + i];
            #pragma unroll
            for (int j = 0; j < TN; j++) br[j] = Bs[kk][tcol * TN + j];
            #pragma unroll
            for (int i = 0; i < TM; i++)
                #pragma unroll
                for (int j = 0; j < TN; j++)
                    acc[i][j] += ar[i] * br[j];
        }
        __syncthreads();
    }

    #pragma unroll
    for (int i = 0; i < TM; i++) {
        int gr = rowBase + trow * TM + i;
        if (gr < M) {
            float* cp = &C[(size_t)gr * Nn + bx * BN + tcol * TN];
            *reinterpret_cast<float4*>(cp) =
                make_float4(acc[i][0], acc[i][1], acc[i][2], acc[i][3]);
            *reinterpret_cast<float4*>(cp + 4) =
                make_float4(acc[i][4], acc[i][5], acc[i][6], acc[i][7]);
        }
    }
}

// ---------------- aggregation: out[i] = sum_e norm*h[col] + dinv^2*h[i] + b ----
// One CTA per node, D/4 threads, float4 lanes. h = g_h (row stride D).
template <int D, bool RELU>
__global__ void k_agg(const float* __restrict__ bias, float* __restrict__ out_override) {
    const int i = blockIdx.x;
    const int t = threadIdx.x;            // 0 .. D/4-1
    const int beg = g_rowptr[i];
    const int end = g_rowptr[i + 1];
    const float di = g_dinv[i];
    const float4* __restrict__ h4 = reinterpret_cast<const float4*>(g_h);

    float4 acc = h4[(size_t)i * (D / 4) + t];
    const float s = di * di;
    acc.x *= s; acc.y *= s; acc.z *= s; acc.w *= s;

    for (int e = beg; e < end; e++) {
        int c = g_col[e];
        float w = g_norm[e];
        float4 v = h4[(size_t)c * (D / 4) + t];
        acc.x += w * v.x;
        acc.y += w * v.y;
        acc.z += w * v.z;
        acc.w += w * v.w;
    }

    float4 bv = reinterpret_cast<const float4*>(bias)[t];
    acc.x += bv.x; acc.y += bv.y; acc.z += bv.z; acc.w += bv.w;
    if (RELU) {
        acc.x = fmaxf(acc.x, 0.f);
        acc.y = fmaxf(acc.y, 0.f);
        acc.z = fmaxf(acc.z, 0.f);
        acc.w = fmaxf(acc.w, 0.f);
    }
    float4* o4 = out_override ? reinterpret_cast<float4*>(out_override)
                              : reinterpret_cast<float4*>(g_x);
    o4[(size_t)i * (D / 4) + t] = acc;
}

// ---------------- launch ----------------
extern "C" void kernel_launch(void* const* d_in, const int* in_sizes, int n_in,
                              void* d_out, int out_size) {
    const float* qe  = (const float*)d_in[0];
    const float* obj = (const float*)d_in[1];
    const int*   ei  = (const int*)d_in[2];     // int32: [0..NE) = dst row, [NE..2NE) = src col
    const float* W1 = (const float*)d_in[3];
    const float* b1 = (const float*)d_in[4];
    const float* W2 = (const float*)d_in[5];
    const float* b2 = (const float*)d_in[6];
    const float* W3 = (const float*)d_in[7];
    const float* b3 = (const float*)d_in[8];
    float* out = (float*)d_out;

    // x = qe * obj
    k_had<<<(NN * DI / 4 + 255) / 256, 256>>>((const float4*)qe, (const float4*)obj);

    // graph prep: degrees, dinv, CSR (by destination), edge norms
    k_zero_deg<<<(NN + 255) / 256, 256>>>();
    k_count<<<(NE + 255) / 256, 256>>>(ei);
    k_dinv<<<(NN + 255) / 256, 256>>>();
    const int nsb = (NN + 1023) / 1024;   // 49
    k_scan_block<<<nsb, 1024>>>();
    k_scan_sums<<<1, 32>>>(nsb);
    k_scan_add<<<(NN + 255) / 256, 256>>>();
    k_fill<<<(NE + 255) / 256, 256>>>(ei);

    // layer 1: h = x@W1 ; x = relu(agg(h) + b1)
    k_sgemm<<<dim3(2, (NN + 127) / 128), 256>>>(W1, NN, DI, DI);
    k_agg<DI, true><<<NN, DI / 4>>>(b1, nullptr);

    // layer 2
    k_sgemm<<<dim3(2, (NN + 127) / 128), 256>>>(W2, NN, DI, DI);
    k_agg<DI, true><<<NN, DI / 4>>>(b2, nullptr);

    // layer 3 (no relu) -> d_out
    k_sgemm<<<dim3(1, (NN + 127) / 128), 256>>>(W3, NN, DI, DO);
    k_agg<DO, false><<<NN, DO / 4>>>(b3, out);
}

// round 5
// speedup vs baseline: 1.7032x; 1.7032x over previous
#include <cuda_runtime.h>
#include <cuda_bf16.h>
#include <cstdint>

// Problem constants
#define NN 50000
#define NE 800000
#define DI 256        // K for all layers
#define DO 128
#define BM 128
#define BN 128
#define IMG 10240            // 128 rows * 80B padded
#define STAGE (4 * IMG)      // Ah, Al, Bh, Bl

// ---------------- device scratch ----------------
__device__ __nv_bfloat16 g_xh[NN * DI];   // activation hi (bf16)
__device__ __nv_bfloat16 g_xl[NN * DI];   // activation lo (bf16)
__device__ float g_h[NN * DI];            // post-GEMM fp32
__device__ int   g_deg[NN];
__device__ float g_dinv[NN];
__device__ int   g_rowptr[NN + 1];
__device__ int   g_cursor[NN];
__device__ int   g_col[NE];
__device__ float g_norm[NE];
__device__ int   g_bsum[64];

// transposed bf16 weight images: Wt[n][k], k contiguous (256 wide)
__device__ __nv_bfloat16 g_W1h[DI * DI], g_W1l[DI * DI];
__device__ __nv_bfloat16 g_W2h[DI * DI], g_W2l[DI * DI];
__device__ __nv_bfloat16 g_W3h[DO * DI], g_W3l[DO * DI];

// ---------------- small helpers ----------------
__device__ __forceinline__ uint32_t smem_u32(const void* p) {
    uint32_t a;
    asm("{ .reg .u64 t; cvta.to.shared.u64 t, %1; cvt.u32.u64 %0, t; }" : "=r"(a) : "l"(p));
    return a;
}
__device__ __forceinline__ uint32_t pk2(float a, float b) {
    __nv_bfloat162 t = __floats2bfloat162_rn(a, b);
    return *reinterpret_cast<uint32_t*>(&t);
}
__device__ __forceinline__ void cpa16(uint32_t dst, const void* src, uint32_t sz) {
    asm volatile("cp.async.cg.shared.global [%0], [%1], 16, %2;"
                 :: "r"(dst), "l"(src), "r"(sz));
}
#define CP_COMMIT() asm volatile("cp.async.commit_group;" ::: "memory")
#define CP_WAIT1()  asm volatile("cp.async.wait_group 1;" ::: "memory")
#define CP_WAIT0()  asm volatile("cp.async.wait_group 0;" ::: "memory")

#define LDSM4(r, a) \
    asm volatile("ldmatrix.sync.aligned.m8n8.x4.shared.b16 {%0,%1,%2,%3}, [%4];" \
                 : "=r"((r)[0]), "=r"((r)[1]), "=r"((r)[2]), "=r"((r)[3]) : "r"(a))

#define MMA(ac, a, bb0, bb1) \
    asm volatile("mma.sync.aligned.m16n8k16.row.col.f32.bf16.bf16.f32 " \
                 "{%0,%1,%2,%3},{%4,%5,%6,%7},{%8,%9},{%0,%1,%2,%3};" \
                 : "+f"((ac)[0]), "+f"((ac)[1]), "+f"((ac)[2]), "+f"((ac)[3]) \
                 : "r"((a)[0]), "r"((a)[1]), "r"((a)[2]), "r"((a)[3]), \
                   "r"(bb0), "r"(bb1))

// ---------------- elementwise: x = qe * obj -> bf16 hi/lo ----------------
__global__ void k_had(const float4* __restrict__ a, const float4* __restrict__ b) {
    int i = blockIdx.x * blockDim.x + threadIdx.x;
    const int n4 = NN * DI / 4;
    if (i < n4) {
        float4 va = a[i], vb = b[i];
        float v0 = va.x * vb.x, v1 = va.y * vb.y, v2 = va.z * vb.z, v3 = va.w * vb.w;
        float h0 = __bfloat162float(__float2bfloat16_rn(v0));
        float h1 = __bfloat162float(__float2bfloat16_rn(v1));
        float h2 = __bfloat162float(__float2bfloat16_rn(v2));
        float h3 = __bfloat162float(__float2bfloat16_rn(v3));
        reinterpret_cast<uint2*>(g_xh)[i] = make_uint2(pk2(h0, h1), pk2(h2, h3));
        reinterpret_cast<uint2*>(g_xl)[i] =
            make_uint2(pk2(v0 - h0, v1 - h1), pk2(v2 - h2, v3 - h3));
    }
}

// ---------------- graph prep ----------------
__global__ void k_zero_deg() {
    int i = blockIdx.x * blockDim.x + threadIdx.x;
    if (i < NN) g_deg[i] = 0;
}
__global__ void k_count(const int* __restrict__ ei) {
    int e = blockIdx.x * blockDim.x + threadIdx.x;
    if (e < NE) atomicAdd(&g_deg[ei[e]], 1);
}
__global__ void k_dinv() {
    int i = blockIdx.x * blockDim.x + threadIdx.x;
    if (i < NN) g_dinv[i] = rsqrtf((float)(g_deg[i] + 1));
}
__global__ __launch_bounds__(1024) void k_scan_block() {
    __shared__ int s[1024];
    int tid = threadIdx.x;
    int i = blockIdx.x * 1024 + tid;
    int v = (i < NN) ? g_deg[i] : 0;
    s[tid] = v;
    __syncthreads();
    #pragma unroll
    for (int off = 1; off < 1024; off <<= 1) {
        int t = (tid >= off) ? s[tid - off] : 0;
        __syncthreads();
        s[tid] += t;
        __syncthreads();
    }
    if (i < NN) g_rowptr[i] = s[tid] - v;
    if (tid == 1023) g_bsum[blockIdx.x] = s[1023];
}
__global__ void k_scan_sums(int nblocks) {
    if (threadIdx.x == 0) {
        int acc = 0;
        for (int b = 0; b < nblocks; b++) { int v = g_bsum[b]; g_bsum[b] = acc; acc += v; }
    }
}
__global__ void k_scan_add() {
    int i = blockIdx.x * blockDim.x + threadIdx.x;
    if (i < NN) {
        int v = g_rowptr[i] + g_bsum[i >> 10];
        g_rowptr[i] = v;
        g_cursor[i] = v;
        if (i == 0) g_rowptr[NN] = NE;
    }
}
__global__ void k_fill(const int* __restrict__ ei) {
    int e = blockIdx.x * blockDim.x + threadIdx.x;
    if (e < NE) {
        int r = ei[e], c = ei[NE + e];
        int pos = atomicAdd(&g_cursor[r], 1);
        g_col[pos]  = c;
        g_norm[pos] = g_dinv[r] * g_dinv[c];
    }
}

// ---------------- weight pack: W[k][n] fp32 -> Wt hi/lo bf16 [n][k] ------
template <int N>
__global__ void k_pack(const float* __restrict__ W, int layer) {
    __nv_bfloat16* Wh = (layer == 0) ? g_W1h : (layer == 1) ? g_W2h : g_W3h;
    __nv_bfloat16* Wl = (layer == 0) ? g_W1l : (layer == 1) ? g_W2l : g_W3l;
    int idx = blockIdx.x * blockDim.x + threadIdx.x;
    if (idx >= DI * N) return;
    int k = idx / N, n = idx % N;
    float w = W[idx];
    __nv_bfloat16 hi = __float2bfloat16_rn(w);
    float hf = __bfloat162float(hi);
    Wh[n * DI + k] = hi;
    Wl[n * DI + k] = __float2bfloat16_rn(w - hf);
}

// ---------------- bf16-split tensor-core GEMM ----------------
// g_h[M,N] = (xh+xl)[M,256] @ (Wh+Wl)^T  (drop lo*lo term), fp32 accum
template <int N>
__global__ __launch_bounds__(256) void k_mma(int layer) {
    const __nv_bfloat16* Wh = (layer == 0) ? g_W1h : (layer == 1) ? g_W2h : g_W3h;
    const __nv_bfloat16* Wl = (layer == 0) ? g_W1l : (layer == 1) ? g_W2l : g_W3l;

    extern __shared__ char smem[];
    const uint32_t sb = smem_u32(smem);
    const int tid = threadIdx.x;
    const int lane = tid & 31, wid = tid >> 5;
    const int wm = (wid >> 1) * 32;        // warp M offset (0,32,64,96)
    const int wn = (wid & 1) * 64;         // warp N offset (0,64)
    const int rowBase = blockIdx.y * BM;
    const int n0 = blockIdx.x * BN;

    float acc[2][8][4];
    #pragma unroll
    for (int a = 0; a < 2; a++)
        #pragma unroll
        for (int b = 0; b < 8; b++)
            #pragma unroll
            for (int c = 0; c < 4; c++) acc[a][b][c] = 0.f;

    // --- stage fill via cp.async: 2048 16B chunks ---
    auto fill = [&](int s, int k0) {
        #pragma unroll
        for (int i = 0; i < 8; i++) {
            int c = tid + i * 256;
            int img = c >> 9;            // 0:Ah 1:Al 2:Bh 3:Bl
            int r   = (c >> 2) & 127;
            int ch  = c & 3;
            uint32_t dst = sb + s * STAGE + img * IMG + r * 80 + ch * 16;
            const __nv_bfloat16* src;
            uint32_t sz = 16;
            if (img < 2) {
                int gr = rowBase + r;
                const __nv_bfloat16* p = (img == 0) ? g_xh : g_xl;
                if (gr >= NN) { gr = 0; sz = 0; }
                src = p + (size_t)gr * DI + k0 + ch * 8;
            } else {
                const __nv_bfloat16* p = (img == 2) ? Wh : Wl;
                src = p + (size_t)(n0 + r) * DI + k0 + ch * 8;
            }
            cpa16(dst, src, sz);
        }
    };

    fill(0, 0);
    CP_COMMIT();

    for (int step = 0; step < 8; step++) {
        const int s = step & 1;
        if (step < 7) { fill(s ^ 1, (step + 1) * 32); CP_COMMIT(); CP_WAIT1(); }
        else CP_WAIT0();
        __syncthreads();

        const uint32_t Ah = sb + s * STAGE;
        const uint32_t Al = Ah + IMG;
        const uint32_t Bh = Ah + 2 * IMG;
        const uint32_t Bl = Ah + 3 * IMG;

        #pragma unroll
        for (int ks = 0; ks < 2; ks++) {
            uint32_t ah[2][4], al[2][4], bh[4][4], bl[4][4];
            // A fragments: row = wm + mt*16 + lane%8 + ((lane>>3)&1)*8 ; k byte = ks*32 + (lane>>4)*16
            const int arow = (lane & 7) + ((lane >> 3) & 1) * 8;
            const int akb  = ks * 32 + (lane >> 4) * 16;
            #pragma unroll
            for (int mt = 0; mt < 2; mt++) {
                uint32_t off = (uint32_t)(wm + mt * 16 + arow) * 80 + akb;
                LDSM4(ah[mt], Ah + off);
                LDSM4(al[mt], Al + off);
            }
            // B fragments: nrow = wn + p*16 + lane%8 + ((lane>>4)&1)*8 ; k byte = ks*32 + ((lane>>3)&1)*16
            const int brow = (lane & 7) + ((lane >> 4) & 1) * 8;
            const int bkb  = ks * 32 + ((lane >> 3) & 1) * 16;
            #pragma unroll
            for (int p = 0; p < 4; p++) {
                uint32_t off = (uint32_t)(wn + p * 16 + brow) * 80 + bkb;
                LDSM4(bh[p], Bh + off);
                LDSM4(bl[p], Bl + off);
            }
            #pragma unroll
            for (int mt = 0; mt < 2; mt++)
                #pragma unroll
                for (int p = 0; p < 4; p++) {
                    MMA(acc[mt][2 * p],     ah[mt], bh[p][0], bh[p][1]);
                    MMA(acc[mt][2 * p + 1], ah[mt], bh[p][2], bh[p][3]);
                    MMA(acc[mt][2 * p],     ah[mt], bl[p][0], bl[p][1]);
                    MMA(acc[mt][2 * p + 1], ah[mt], bl[p][2], bl[p][3]);
                    MMA(acc[mt][2 * p],     al[mt], bh[p][0], bh[p][1]);
                    MMA(acc[mt][2 * p + 1], al[mt], bh[p][2], bh[p][3]);
                }
        }
        __syncthreads();
    }

    // --- epilogue: write fp32 to g_h ---
    const int g = lane >> 2, t2 = (lane & 3) * 2;
    #pragma unroll
    for (int mt = 0; mt < 2; mt++) {
        int r0 = rowBase + wm + mt * 16 + g;
        #pragma unroll
        for (int nt = 0; nt < 8; nt++) {
            int col = n0 + wn + nt * 8 + t2;
            if (r0 < NN)
                *reinterpret_cast<float2*>(&g_h[(size_t)r0 * N + col]) =
                    make_float2(acc[mt][nt][0], acc[mt][nt][1]);
            if (r0 + 8 < NN)
                *reinterpret_cast<float2*>(&g_h[(size_t)(r0 + 8) * N + col]) =
                    make_float2(acc[mt][nt][2], acc[mt][nt][3]);
        }
    }
}

// ---------------- aggregation ----------------
// HIDDEN=true: relu + write bf16 hi/lo (next GEMM input). else: write fp32 out.
template <int D, bool HIDDEN>
__global__ void k_agg(const float* __restrict__ bias, float* __restrict__ outp) {
    const int i = blockIdx.x;
    const int t = threadIdx.x;
    const int beg = g_rowptr[i];
    const int end = g_rowptr[i + 1];
    const float di = g_dinv[i];
    const float4* __restrict__ h4 = reinterpret_cast<const float4*>(g_h);

    float4 acc = h4[(size_t)i * (D / 4) + t];
    const float s = di * di;
    acc.x *= s; acc.y *= s; acc.z *= s; acc.w *= s;

    for (int e = beg; e < end; e++) {
        int c = g_col[e];
        float w = g_norm[e];
        float4 v = h4[(size_t)c * (D / 4) + t];
        acc.x += w * v.x; acc.y += w * v.y; acc.z += w * v.z; acc.w += w * v.w;
    }

    float4 bv = reinterpret_cast<const float4*>(bias)[t];
    acc.x += bv.x; acc.y += bv.y; acc.z += bv.z; acc.w += bv.w;

    if (HIDDEN) {
        acc.x = fmaxf(acc.x, 0.f); acc.y = fmaxf(acc.y, 0.f);
        acc.z = fmaxf(acc.z, 0.f); acc.w = fmaxf(acc.w, 0.f);
        float h0 = __bfloat162float(__float2bfloat16_rn(acc.x));
        float h1 = __bfloat162float(__float2bfloat16_rn(acc.y));
        float h2 = __bfloat162float(__float2bfloat16_rn(acc.z));
        float h3 = __bfloat162float(__float2bfloat16_rn(acc.w));
        size_t o = (size_t)i * (D / 4) + t;
        reinterpret_cast<uint2*>(g_xh)[o] = make_uint2(pk2(h0, h1), pk2(h2, h3));
        reinterpret_cast<uint2*>(g_xl)[o] =
            make_uint2(pk2(acc.x - h0, acc.y - h1), pk2(acc.z - h2, acc.w - h3));
    } else {
        reinterpret_cast<float4*>(outp)[(size_t)i * (D / 4) + t] = acc;
    }
}

// ---------------- launch ----------------
extern "C" void kernel_launch(void* const* d_in, const int* in_sizes, int n_in,
                              void* d_out, int out_size) {
    const float* qe  = (const float*)d_in[0];
    const float* obj = (const float*)d_in[1];
    const int*   ei  = (const int*)d_in[2];
    const float* W1 = (const float*)d_in[3];
    const float* b1 = (const float*)d_in[4];
    const float* W2 = (const float*)d_in[5];
    const float* b2 = (const float*)d_in[6];
    const float* W3 = (const float*)d_in[7];
    const float* b3 = (const float*)d_in[8];
    float* out = (float*)d_out;

    const int SMEM = 2 * STAGE;   // 81920
    static bool attr_done = false;
    if (!attr_done) {
        cudaFuncSetAttribute(k_mma<256>, cudaFuncAttributeMaxDynamicSharedMemorySize, SMEM);
        cudaFuncSetAttribute(k_mma<128>, cudaFuncAttributeMaxDynamicSharedMemorySize, SMEM);
        attr_done = true;
    }

    // x = qe * obj (bf16 hi/lo)
    k_had<<<(NN * DI / 4 + 255) / 256, 256>>>((const float4*)qe, (const float4*)obj);

    // graph prep
    k_zero_deg<<<(NN + 255) / 256, 256>>>();
    k_count<<<(NE + 255) / 256, 256>>>(ei);
    k_dinv<<<(NN + 255) / 256, 256>>>();
    const int nsb = (NN + 1023) / 1024;
    k_scan_block<<<nsb, 1024>>>();
    k_scan_sums<<<1, 32>>>(nsb);
    k_scan_add<<<(NN + 255) / 256, 256>>>();
    k_fill<<<(NE + 255) / 256, 256>>>(ei);

    // weight pack (transposed hi/lo bf16)
    k_pack<256><<<(DI * DI + 255) / 256, 256>>>(W1, 0);
    k_pack<256><<<(DI * DI + 255) / 256, 256>>>(W2, 1);
    k_pack<128><<<(DI * DO + 255) / 256, 256>>>(W3, 2);

    const int mb = (NN + BM - 1) / BM;    // 391

    // layer 1
    k_mma<256><<<dim3(2, mb), 256, SMEM>>>(0);
    k_agg<DI, true><<<NN, DI / 4>>>(b1, nullptr);
    // layer 2
    k_mma<256><<<dim3(2, mb), 256, SMEM>>>(1);
    k_agg<DI, true><<<NN, DI / 4>>>(b2, nullptr);
    // layer 3
    k_mma<128><<<dim3(1, mb), 256, SMEM>>>(2);
    k_agg<DO, false><<<NN, DO / 4>>>(b3, out);
}